// round 2
// baseline (speedup 1.0000x reference)
#include <cuda_runtime.h>

typedef unsigned long long ULL;

// ---------------- f32x2 helpers (Blackwell packed fp32) ----------------
__device__ __forceinline__ ULL pk2(float a, float b) {
    ULL r; asm("mov.b64 %0, {%1, %2};" : "=l"(r) : "f"(a), "f"(b)); return r;
}
__device__ __forceinline__ void upk2(ULL v, float& a, float& b) {
    asm("mov.b64 {%0, %1}, %2;" : "=f"(a), "=f"(b) : "l"(v));
}
#define FMA2(acc, a, b) asm("fma.rn.f32x2 %0, %1, %2, %0;" : "+l"(acc) : "l"(a), "l"(b))

// ---------------- problem constants ----------------
constexpr int B_  = 4096;
constexpr int T_  = 128;
constexpr int I_  = 28;
constexpr int O_  = 10;
constexpr int RPB = 32;            // batch rows per block
constexpr int NBLK = B_ / RPB;     // 128 blocks
constexpr int NTHR = 256;
constexpr int LDD  = 68;           // duplicated-row stride (floats): 64 data + 4 pad, 16B-aligned rows

// shared memory layout (floats)
// Ws[k][j*4 + q], q in {i,f,g,o}; k: 0..63 = W_hh rows (h index), 64..91 = W_ih rows (x index)
constexpr int WS_ELE  = 92 * 256;
constexpr int HD_OFF  = WS_ELE;                 // hdup[64][LDD]   (unit k major; (h,h) pairs over rows)
constexpr int XD_OFF  = HD_OFF + 64 * LDD;      // xdup[2][28][LDD] double buffer, (x,x) pairs
constexpr int SM_FLOATS = XD_OFF + 2 * 28 * LDD;   // ~126.8 KB

// ---------------- activations (accurate, exp-based) ----------------
__device__ __forceinline__ float sigf(float x) {
    return __fdividef(1.0f, 1.0f + __expf(-x));
}
__device__ __forceinline__ float tanh_(float x) {
    float ax = fabsf(x);
    float e  = __expf(-2.0f * ax);
    float r  = __fdividef(1.0f - e, 1.0f + e);
    return copysignf(r, x);
}

__global__ void __launch_bounds__(NTHR, 1) lstm_fused(
    const float* __restrict__ x,     // [B, T, I]
    const float* __restrict__ Wih,   // [4H, I]
    const float* __restrict__ Whh,   // [4H, H]
    const float* __restrict__ bih,   // [4H]
    const float* __restrict__ bhh,   // [4H]
    const float* __restrict__ Wout,  // [O, H]
    const float* __restrict__ bout,  // [O]
    float* __restrict__ out)         // [B, O]
{
    extern __shared__ float sm[];
    float* Ws   = sm;
    float* hdup = sm + HD_OFF;
    float* xdup = sm + XD_OFF;

    const int tid   = threadIdx.x;
    const int j     = tid & 63;   // hidden unit owned by this thread
    const int ty    = tid >> 6;   // row group (0..3), 8 rows each
    const int rbase = ty * 8;
    const int row0  = blockIdx.x * RPB;

    // ---- stage weights into SMEM, gate-interleaved: Ws[k][j*4 + q] ----
    for (int idx = tid; idx < 256 * 64; idx += NTHR) {        // W_hh[g][k]
        int g = idx >> 6, k = idx & 63;
        Ws[k * 256 + (g & 63) * 4 + (g >> 6)] = Whh[idx];
    }
    for (int idx = tid; idx < 256 * 28; idx += NTHR) {        // W_ih[g][k]
        int g = idx / 28, k = idx - g * 28;
        Ws[(64 + k) * 256 + (g & 63) * 4 + (g >> 6)] = Wih[idx];
    }
    for (int idx = tid; idx < 64 * LDD; idx += NTHR) hdup[idx] = 0.0f;

    // biases (combined), packed as gate pairs: (b_i,b_f) and (b_g,b_o)
    const float b0 = bih[j]       + bhh[j];
    const float b1 = bih[64 + j]  + bhh[64 + j];
    const float b2 = bih[128 + j] + bhh[128 + j];
    const float b3 = bih[192 + j] + bhh[192 + j];
    const ULL bif = pk2(b0, b1);
    const ULL bgo = pk2(b2, b3);

    // ---- preload x for t = 0 into buffer 0 (duplicated pairs) ----
    if (tid < 224) {
        #pragma unroll
        for (int u = 0; u < 4; ++u) {
            int e = u * 224 + tid;
            int r = e / 28, i2 = e - r * 28;
            float v = x[(row0 + r) * (T_ * I_) + 0 * I_ + i2];
            *reinterpret_cast<ULL*>(xdup + i2 * LDD + 2 * r) = pk2(v, v);
        }
    }
    __syncthreads();

    float creg[8];
    #pragma unroll
    for (int r = 0; r < 8; ++r) creg[r] = 0.0f;

    // =================== time loop ===================
    for (int t = 0; t < T_; ++t) {
        // prefetch x for t+1 (LDG latency overlaps this step's compute)
        float xn[4];
        const bool pf = (t + 1 < T_) && (tid < 224);
        if (pf) {
            #pragma unroll
            for (int u = 0; u < 4; ++u) {
                int e = u * 224 + tid;
                int r = e / 28, i2 = e - r * 28;
                xn[u] = x[(row0 + r) * (T_ * I_) + (t + 1) * I_ + i2];
            }
        }

        const float* xb = xdup + (t & 1) * 28 * LDD;

        // accumulators: [row r][pair p], pair 0 = (i,f), pair 1 = (g,o)
        ULL acc[8][2];
        #pragma unroll
        for (int r = 0; r < 8; ++r) { acc[r][0] = bif; acc[r][1] = bgo; }

        // ---- recurrent part: k over hidden units (h_{t-1}) ----
        #pragma unroll 4
        for (int k = 0; k < 64; ++k) {
            const ulonglong2 w = *reinterpret_cast<const ulonglong2*>(Ws + k * 256 + j * 4);
            const float* hb = hdup + k * LDD + 2 * rbase;
            const ulonglong2 hA = *reinterpret_cast<const ulonglong2*>(hb);       // rows r0,r1 (dup)
            const ulonglong2 hB = *reinterpret_cast<const ulonglong2*>(hb + 4);   // r2,r3
            const ulonglong2 hC = *reinterpret_cast<const ulonglong2*>(hb + 8);   // r4,r5
            const ulonglong2 hD = *reinterpret_cast<const ulonglong2*>(hb + 12);  // r6,r7
            FMA2(acc[0][0], hA.x, w.x); FMA2(acc[0][1], hA.x, w.y);
            FMA2(acc[1][0], hA.y, w.x); FMA2(acc[1][1], hA.y, w.y);
            FMA2(acc[2][0], hB.x, w.x); FMA2(acc[2][1], hB.x, w.y);
            FMA2(acc[3][0], hB.y, w.x); FMA2(acc[3][1], hB.y, w.y);
            FMA2(acc[4][0], hC.x, w.x); FMA2(acc[4][1], hC.x, w.y);
            FMA2(acc[5][0], hC.y, w.x); FMA2(acc[5][1], hC.y, w.y);
            FMA2(acc[6][0], hD.x, w.x); FMA2(acc[6][1], hD.x, w.y);
            FMA2(acc[7][0], hD.y, w.x); FMA2(acc[7][1], hD.y, w.y);
        }
        // ---- input part: k over I (x_t) ----
        #pragma unroll 4
        for (int k = 0; k < 28; ++k) {
            const ulonglong2 w = *reinterpret_cast<const ulonglong2*>(Ws + (64 + k) * 256 + j * 4);
            const float* hb = xb + k * LDD + 2 * rbase;
            const ulonglong2 hA = *reinterpret_cast<const ulonglong2*>(hb);
            const ulonglong2 hB = *reinterpret_cast<const ulonglong2*>(hb + 4);
            const ulonglong2 hC = *reinterpret_cast<const ulonglong2*>(hb + 8);
            const ulonglong2 hD = *reinterpret_cast<const ulonglong2*>(hb + 12);
            FMA2(acc[0][0], hA.x, w.x); FMA2(acc[0][1], hA.x, w.y);
            FMA2(acc[1][0], hA.y, w.x); FMA2(acc[1][1], hA.y, w.y);
            FMA2(acc[2][0], hB.x, w.x); FMA2(acc[2][1], hB.x, w.y);
            FMA2(acc[3][0], hB.y, w.x); FMA2(acc[3][1], hB.y, w.y);
            FMA2(acc[4][0], hC.x, w.x); FMA2(acc[4][1], hC.x, w.y);
            FMA2(acc[5][0], hC.y, w.x); FMA2(acc[5][1], hC.y, w.y);
            FMA2(acc[6][0], hD.x, w.x); FMA2(acc[6][1], hD.x, w.y);
            FMA2(acc[7][0], hD.y, w.x); FMA2(acc[7][1], hD.y, w.y);
        }

        // ---- elementwise LSTM cell update (c stays in registers) ----
        float hnew[8];
        #pragma unroll
        for (int r = 0; r < 8; ++r) {
            float gi, gf, gg, go;
            upk2(acc[r][0], gi, gf);
            upk2(acc[r][1], gg, go);
            float iv = sigf(gi), fv = sigf(gf), gv = tanh_(gg), ov = sigf(go);
            creg[r] = fv * creg[r] + iv * gv;
            hnew[r] = ov * tanh_(creg[r]);
        }

        __syncthreads();   // everyone done reading hdup / xdup[t&1]

        // write new h (duplicated: hdup[unit][2*row] = (h,h)); stage next x tile
        {
            ULL* hd = reinterpret_cast<ULL*>(hdup + j * LDD + 2 * rbase);
            #pragma unroll
            for (int r = 0; r < 8; ++r) hd[r] = pk2(hnew[r], hnew[r]);
        }
        if (pf) {
            float* xb2 = xdup + ((t + 1) & 1) * 28 * LDD;
            #pragma unroll
            for (int u = 0; u < 4; ++u) {
                int e = u * 224 + tid;
                int r = e / 28, i2 = e - r * 28;
                *reinterpret_cast<ULL*>(xb2 + i2 * LDD + 2 * r) = pk2(xn[u], xn[u]);
            }
        }
        __syncthreads();
    }

    // ---- final projection: out[b][o] = h_T[b] . Wout[o] + bout[o] ----
    for (int idx = tid; idx < RPB * O_; idx += NTHR) {
        int r = idx / O_, o = idx - r * O_;
        float s = bout[o];
        #pragma unroll
        for (int k = 0; k < 64; ++k)
            s += hdup[k * LDD + 2 * r] * Wout[o * 64 + k];
        out[(row0 + r) * O_ + o] = s;
    }
}

extern "C" void kernel_launch(void* const* d_in, const int* in_sizes, int n_in,
                              void* d_out, int out_size)
{
    const float* x    = (const float*)d_in[0];
    const float* Wih  = (const float*)d_in[1];
    const float* Whh  = (const float*)d_in[2];
    const float* bih  = (const float*)d_in[3];
    const float* bhh  = (const float*)d_in[4];
    const float* Wout = (const float*)d_in[5];
    const float* bout = (const float*)d_in[6];
    float* out = (float*)d_out;

    const size_t smem = (size_t)SM_FLOATS * sizeof(float);  // ~126.8 KB
    cudaFuncSetAttribute(lstm_fused, cudaFuncAttributeMaxDynamicSharedMemorySize, (int)smem);
    lstm_fused<<<NBLK, NTHR, smem>>>(x, Wih, Whh, bih, bhh, Wout, bout, out);
}

// round 3
// speedup vs baseline: 1.9155x; 1.9155x over previous
#include <cuda_runtime.h>

typedef unsigned long long ULL;

// ---------------- f32x2 helpers (Blackwell packed fp32) ----------------
__device__ __forceinline__ ULL pk2(float a, float b) {
    ULL r; asm("mov.b64 %0, {%1, %2};" : "=l"(r) : "f"(a), "f"(b)); return r;
}
__device__ __forceinline__ void upk2(ULL v, float& a, float& b) {
    asm("mov.b64 {%0, %1}, %2;" : "=f"(a), "=f"(b) : "l"(v));
}
#define FMA2(acc, a, b) asm("fma.rn.f32x2 %0, %1, %2, %0;" : "+l"(acc) : "l"(a), "l"(b))

// ---------------- problem constants ----------------
constexpr int B_  = 4096;
constexpr int T_  = 128;
constexpr int I_  = 28;
constexpr int O_  = 10;
constexpr int RPB = 16;            // batch rows per block (halved: 2 CTAs co-resident per SM)
constexpr int NBLK = B_ / RPB;     // 256 blocks
constexpr int NTHR = 128;          // 64 units x 2 row-groups
constexpr int LDH  = 18;           // padded row length (floats): even -> 8B-aligned pairs, 2-way STS conflicts only

// shared memory layout (floats), per CTA
constexpr int WS_ELE  = 92 * 256;             // Ws[k][j*4+q], k: 0..63 = W_hh, 64..91 = W_ih
constexpr int HT_OFF  = WS_ELE;               // hT[64][LDH]  (unit-major, rows contiguous)
constexpr int XT_OFF  = HT_OFF + 64 * LDH;    // xT[2][28][LDH] double buffer
constexpr int SM_FLOATS = XT_OFF + 2 * 28 * LDH;   // ~102.8 KB -> two CTAs fit per SM

// ---------------- activations (accurate, exp-based) ----------------
__device__ __forceinline__ float sigf(float x) {
    return __fdividef(1.0f, 1.0f + __expf(-x));
}
__device__ __forceinline__ float tanh_(float x) {
    float ax = fabsf(x);
    float e  = __expf(-2.0f * ax);
    float r  = __fdividef(1.0f - e, 1.0f + e);
    return copysignf(r, x);
}

__global__ void __launch_bounds__(NTHR, 2) lstm_fused(
    const float* __restrict__ x,     // [B, T, I]
    const float* __restrict__ Wih,   // [4H, I]
    const float* __restrict__ Whh,   // [4H, H]
    const float* __restrict__ bih,   // [4H]
    const float* __restrict__ bhh,   // [4H]
    const float* __restrict__ Wout,  // [O, H]
    const float* __restrict__ bout,  // [O]
    float* __restrict__ out)         // [B, O]
{
    extern __shared__ float sm[];
    float* Ws = sm;
    float* hT = sm + HT_OFF;
    float* xT = sm + XT_OFF;

    const int tid   = threadIdx.x;
    const int j     = tid & 63;   // hidden unit owned by this thread
    const int ty    = tid >> 6;   // row group (0..1), 8 rows each
    const int rbase = ty * 8;
    const int row0  = blockIdx.x * RPB;

    // ---- stage weights into SMEM, gate-interleaved: Ws[k][j*4 + q], q in {i,f,g,o} ----
    for (int idx = tid; idx < 256 * 64; idx += NTHR) {        // W_hh[g][k], coalesced read
        int g = idx >> 6, k = idx & 63;
        Ws[k * 256 + (g & 63) * 4 + (g >> 6)] = Whh[idx];
    }
    for (int idx = tid; idx < 256 * 28; idx += NTHR) {        // W_ih[g][k]
        int g = idx / 28, k = idx - g * 28;
        Ws[(64 + k) * 256 + (g & 63) * 4 + (g >> 6)] = Wih[idx];
    }
    for (int idx = tid; idx < 64 * LDH; idx += NTHR) hT[idx] = 0.0f;

    // biases (combined), replicated into f32x2
    const float b0 = bih[j]       + bhh[j];
    const float b1 = bih[64 + j]  + bhh[64 + j];
    const float b2 = bih[128 + j] + bhh[128 + j];
    const float b3 = bih[192 + j] + bhh[192 + j];
    const ULL bb[4] = { pk2(b0, b0), pk2(b1, b1), pk2(b2, b2), pk2(b3, b3) };

    // ---- preload x for t = 0 into buffer 0 ----  (RPB*I = 448 elements, 128 threads)
    #pragma unroll
    for (int u = 0; u < 4; ++u) {
        int e = u * NTHR + tid;
        if (e < RPB * I_) {
            int r = e / 28, i2 = e - r * 28;
            xT[i2 * LDH + r] = x[(row0 + r) * (T_ * I_) + 0 * I_ + i2];
        }
    }
    __syncthreads();

    float creg[8];
    #pragma unroll
    for (int r = 0; r < 8; ++r) creg[r] = 0.0f;

    // =================== time loop ===================
    for (int t = 0; t < T_; ++t) {
        // prefetch x for t+1 (LDG latency overlaps this step's compute)
        float xn[4];
        const bool pf = (t + 1 < T_);
        if (pf) {
            #pragma unroll
            for (int u = 0; u < 4; ++u) {
                int e = u * NTHR + tid;
                if (e < RPB * I_) {
                    int r = e / 28, i2 = e - r * 28;
                    xn[u] = x[(row0 + r) * (T_ * I_) + (t + 1) * I_ + i2];
                }
            }
        }

        const float* xb = xT + (t & 1) * 28 * LDH;

        // accumulators: [row-pair r2][gate-type q], rows packed in f32x2 lanes
        ULL acc[4][4];
        #pragma unroll
        for (int r2 = 0; r2 < 4; ++r2)
            #pragma unroll
            for (int q = 0; q < 4; ++q)
                acc[r2][q] = bb[q];

        // ---- recurrent part: k over hidden units (h_{t-1}) ----
        #pragma unroll 4
        for (int k = 0; k < 64; ++k) {
            const float4 w4 = *reinterpret_cast<const float4*>(Ws + k * 256 + j * 4);
            const ULL w0 = pk2(w4.x, w4.x), w1 = pk2(w4.y, w4.y);
            const ULL w2 = pk2(w4.z, w4.z), w3 = pk2(w4.w, w4.w);
            const ULL* hp = reinterpret_cast<const ULL*>(hT + k * LDH + rbase);
            const ULL h0 = hp[0], h1 = hp[1], h2 = hp[2], h3 = hp[3];
            FMA2(acc[0][0], h0, w0); FMA2(acc[0][1], h0, w1); FMA2(acc[0][2], h0, w2); FMA2(acc[0][3], h0, w3);
            FMA2(acc[1][0], h1, w0); FMA2(acc[1][1], h1, w1); FMA2(acc[1][2], h1, w2); FMA2(acc[1][3], h1, w3);
            FMA2(acc[2][0], h2, w0); FMA2(acc[2][1], h2, w1); FMA2(acc[2][2], h2, w2); FMA2(acc[2][3], h2, w3);
            FMA2(acc[3][0], h3, w0); FMA2(acc[3][1], h3, w1); FMA2(acc[3][2], h3, w2); FMA2(acc[3][3], h3, w3);
        }
        // ---- input part: k over I (x_t) ----
        #pragma unroll 4
        for (int k = 0; k < 28; ++k) {
            const float4 w4 = *reinterpret_cast<const float4*>(Ws + (64 + k) * 256 + j * 4);
            const ULL w0 = pk2(w4.x, w4.x), w1 = pk2(w4.y, w4.y);
            const ULL w2 = pk2(w4.z, w4.z), w3 = pk2(w4.w, w4.w);
            const ULL* xp = reinterpret_cast<const ULL*>(xb + k * LDH + rbase);
            const ULL h0 = xp[0], h1 = xp[1], h2 = xp[2], h3 = xp[3];
            FMA2(acc[0][0], h0, w0); FMA2(acc[0][1], h0, w1); FMA2(acc[0][2], h0, w2); FMA2(acc[0][3], h0, w3);
            FMA2(acc[1][0], h1, w0); FMA2(acc[1][1], h1, w1); FMA2(acc[1][2], h1, w2); FMA2(acc[1][3], h1, w3);
            FMA2(acc[2][0], h2, w0); FMA2(acc[2][1], h2, w1); FMA2(acc[2][2], h2, w2); FMA2(acc[2][3], h2, w3);
            FMA2(acc[3][0], h3, w0); FMA2(acc[3][1], h3, w1); FMA2(acc[3][2], h3, w2); FMA2(acc[3][3], h3, w3);
        }

        // ---- elementwise LSTM cell update (c stays in registers) ----
        float hnew[8];
        #pragma unroll
        for (int r2 = 0; r2 < 4; ++r2) {
            float gi0, gi1, gf0, gf1, gg0, gg1, go0, go1;
            upk2(acc[r2][0], gi0, gi1);
            upk2(acc[r2][1], gf0, gf1);
            upk2(acc[r2][2], gg0, gg1);
            upk2(acc[r2][3], go0, go1);
            {
                const int r = 2 * r2;
                float iv = sigf(gi0), fv = sigf(gf0), gv = tanh_(gg0), ov = sigf(go0);
                creg[r] = fv * creg[r] + iv * gv;
                hnew[r] = ov * tanh_(creg[r]);
            }
            {
                const int r = 2 * r2 + 1;
                float iv = sigf(gi1), fv = sigf(gf1), gv = tanh_(gg1), ov = sigf(go1);
                creg[r] = fv * creg[r] + iv * gv;
                hnew[r] = ov * tanh_(creg[r]);
            }
        }

        __syncthreads();   // everyone done reading hT / xT[t&1]

        // write new h (transposed: hT[unit][row]); stage next x tile
        float* hd = hT + j * LDH + rbase;
        #pragma unroll
        for (int r = 0; r < 8; ++r) hd[r] = hnew[r];
        if (pf) {
            float* xb2 = xT + ((t + 1) & 1) * 28 * LDH;
            #pragma unroll
            for (int u = 0; u < 4; ++u) {
                int e = u * NTHR + tid;
                if (e < RPB * I_) {
                    int r = e / 28, i2 = e - r * 28;
                    xb2[i2 * LDH + r] = xn[u];
                }
            }
        }
        __syncthreads();
    }

    // ---- final projection: out[b][o] = h_T[b] . Wout[o] + bout[o] ----
    for (int idx = tid; idx < RPB * O_; idx += NTHR) {
        int r = idx / O_, o = idx - r * O_;
        float s = bout[o];
        #pragma unroll
        for (int k = 0; k < 64; ++k)
            s += hT[k * LDH + r] * Wout[o * 64 + k];
        out[(row0 + r) * O_ + o] = s;
    }
}

extern "C" void kernel_launch(void* const* d_in, const int* in_sizes, int n_in,
                              void* d_out, int out_size)
{
    const float* x    = (const float*)d_in[0];
    const float* Wih  = (const float*)d_in[1];
    const float* Whh  = (const float*)d_in[2];
    const float* bih  = (const float*)d_in[3];
    const float* bhh  = (const float*)d_in[4];
    const float* Wout = (const float*)d_in[5];
    const float* bout = (const float*)d_in[6];
    float* out = (float*)d_out;

    const size_t smem = (size_t)SM_FLOATS * sizeof(float);  // ~102.8 KB per CTA
    cudaFuncSetAttribute(lstm_fused, cudaFuncAttributeMaxDynamicSharedMemorySize, (int)smem);
    lstm_fused<<<NBLK, NTHR, smem>>>(x, Wih, Whh, bih, bhh, Wout, bout, out);
}

// round 4
// speedup vs baseline: 2.0353x; 1.0625x over previous
#include <cuda_runtime.h>

typedef unsigned long long ULL;

// ---------------- f32x2 helpers (Blackwell packed fp32) ----------------
__device__ __forceinline__ ULL pk2(float a, float b) {
    ULL r; asm("mov.b64 %0, {%1, %2};" : "=l"(r) : "f"(a), "f"(b)); return r;
}
__device__ __forceinline__ void upk2(ULL v, float& a, float& b) {
    asm("mov.b64 {%0, %1}, %2;" : "=f"(a), "=f"(b) : "l"(v));
}
#define FMA2(acc, a, b) asm("fma.rn.f32x2 %0, %1, %2, %0;" : "+l"(acc) : "l"(a), "l"(b))

// ---------------- problem constants ----------------
constexpr int B_  = 4096;
constexpr int T_  = 128;
constexpr int I_  = 28;
constexpr int O_  = 10;
constexpr int RPB = 16;            // batch rows per block
constexpr int NBLK = B_ / RPB;     // 256 blocks (2 CTAs co-resident on most SMs)
constexpr int NTHR = 128;          // 64 units x 2 row-groups
constexpr int LDH  = 18;           // padded row stride (floats), 8B-aligned pairs

// shared memory layout (floats), per CTA
constexpr int WS_ELE  = 92 * 256;             // Ws[k][j*4+q], k: 0..63 = W_hh, 64..91 = W_ih
constexpr int HT_OFF  = WS_ELE;               // hT[2][64][LDH]  double buffer (unit-major)
constexpr int XT_OFF  = HT_OFF + 2 * 64 * LDH; // xT[2][28][LDH] double buffer
constexpr int SM_FLOATS = XT_OFF + 2 * 28 * LDH;   // ~107.5 KB -> two CTAs fit per SM

// ---------------- activations (accurate, exp-based; identical math to R1) ----------------
__device__ __forceinline__ float sigf(float x) {
    return __fdividef(1.0f, 1.0f + __expf(-x));
}
__device__ __forceinline__ float tanh_(float x) {
    float ax = fabsf(x);
    float e  = __expf(-2.0f * ax);
    float r  = __fdividef(1.0f - e, 1.0f + e);
    return copysignf(r, x);
}

__global__ void __launch_bounds__(NTHR, 2) lstm_fused(
    const float* __restrict__ x,     // [B, T, I]
    const float* __restrict__ Wih,   // [4H, I]
    const float* __restrict__ Whh,   // [4H, H]
    const float* __restrict__ bih,   // [4H]
    const float* __restrict__ bhh,   // [4H]
    const float* __restrict__ Wout,  // [O, H]
    const float* __restrict__ bout,  // [O]
    float* __restrict__ out)         // [B, O]
{
    extern __shared__ float sm[];
    float* Ws = sm;
    float* hT = sm + HT_OFF;   // two buffers of 64*LDH
    float* xT = sm + XT_OFF;

    const int tid   = threadIdx.x;
    const int j     = tid & 63;   // hidden unit owned by this thread
    const int ty    = tid >> 6;   // row group (0..1), 8 rows each
    const int rbase = ty * 8;
    const int row0  = blockIdx.x * RPB;

    // ---- stage weights into SMEM, gate-interleaved: Ws[k][j*4 + q], q in {i,f,g,o} ----
    for (int idx = tid; idx < 256 * 64; idx += NTHR) {        // W_hh[g][k]
        int g = idx >> 6, k = idx & 63;
        Ws[k * 256 + (g & 63) * 4 + (g >> 6)] = Whh[idx];
    }
    for (int idx = tid; idx < 256 * 28; idx += NTHR) {        // W_ih[g][k]
        int g = idx / 28, k = idx - g * 28;
        Ws[(64 + k) * 256 + (g & 63) * 4 + (g >> 6)] = Wih[idx];
    }
    for (int idx = tid; idx < 2 * 64 * LDH; idx += NTHR) hT[idx] = 0.0f;

    // biases (combined), replicated into f32x2
    const float b0 = bih[j]       + bhh[j];
    const float b1 = bih[64 + j]  + bhh[64 + j];
    const float b2 = bih[128 + j] + bhh[128 + j];
    const float b3 = bih[192 + j] + bhh[192 + j];
    const ULL bb[4] = { pk2(b0, b0), pk2(b1, b1), pk2(b2, b2), pk2(b3, b3) };

    // ---- preload x for t = 0 into buffer 0 ----  (RPB*I = 448 elements, 128 threads)
    #pragma unroll
    for (int u = 0; u < 4; ++u) {
        int e = u * NTHR + tid;
        if (e < RPB * I_) {
            int r = e / 28, i2 = e - r * 28;
            xT[i2 * LDH + r] = x[(row0 + r) * (T_ * I_) + 0 * I_ + i2];
        }
    }
    __syncthreads();

    float creg[8];
    #pragma unroll
    for (int r = 0; r < 8; ++r) creg[r] = 0.0f;

    // =================== time loop (ONE barrier per step) ===================
    for (int t = 0; t < T_; ++t) {
        // prefetch x for t+1 (LDG latency overlaps this step's compute)
        float xn[4];
        const bool pf = (t + 1 < T_);
        if (pf) {
            #pragma unroll
            for (int u = 0; u < 4; ++u) {
                int e = u * NTHR + tid;
                int e2 = (e < RPB * I_) ? e : 0;      // branch-free: clamp, lane 0 dup
                int r = e2 / 28, i2 = e2 - r * 28;
                xn[u] = x[(row0 + r) * (T_ * I_) + (t + 1) * I_ + i2];
            }
        }

        const float* xb = xT + (t & 1) * 28 * LDH;
        const float* hb = hT + (t & 1) * 64 * LDH;   // read buffer

        // accumulators: [row-pair r2][gate-type q], rows packed in f32x2 lanes
        ULL acc[4][4];
        #pragma unroll
        for (int r2 = 0; r2 < 4; ++r2)
            #pragma unroll
            for (int q = 0; q < 4; ++q)
                acc[r2][q] = bb[q];

        // ---- recurrent part: k over hidden units (h_{t-1}) ----
        #pragma unroll 8
        for (int k = 0; k < 64; ++k) {
            const float4 w4 = *reinterpret_cast<const float4*>(Ws + k * 256 + j * 4);
            const ULL* hp = reinterpret_cast<const ULL*>(hb + k * LDH + rbase);
            const ULL h0 = hp[0], h1 = hp[1], h2 = hp[2], h3 = hp[3];
            const ULL w0 = pk2(w4.x, w4.x), w1 = pk2(w4.y, w4.y);
            const ULL w2 = pk2(w4.z, w4.z), w3 = pk2(w4.w, w4.w);
            FMA2(acc[0][0], h0, w0); FMA2(acc[0][1], h0, w1); FMA2(acc[0][2], h0, w2); FMA2(acc[0][3], h0, w3);
            FMA2(acc[1][0], h1, w0); FMA2(acc[1][1], h1, w1); FMA2(acc[1][2], h1, w2); FMA2(acc[1][3], h1, w3);
            FMA2(acc[2][0], h2, w0); FMA2(acc[2][1], h2, w1); FMA2(acc[2][2], h2, w2); FMA2(acc[2][3], h2, w3);
            FMA2(acc[3][0], h3, w0); FMA2(acc[3][1], h3, w1); FMA2(acc[3][2], h3, w2); FMA2(acc[3][3], h3, w3);
        }
        // ---- input part: k over I (x_t) ----
        #pragma unroll 4
        for (int k = 0; k < 28; ++k) {
            const float4 w4 = *reinterpret_cast<const float4*>(Ws + (64 + k) * 256 + j * 4);
            const ULL* xp = reinterpret_cast<const ULL*>(xb + k * LDH + rbase);
            const ULL h0 = xp[0], h1 = xp[1], h2 = xp[2], h3 = xp[3];
            const ULL w0 = pk2(w4.x, w4.x), w1 = pk2(w4.y, w4.y);
            const ULL w2 = pk2(w4.z, w4.z), w3 = pk2(w4.w, w4.w);
            FMA2(acc[0][0], h0, w0); FMA2(acc[0][1], h0, w1); FMA2(acc[0][2], h0, w2); FMA2(acc[0][3], h0, w3);
            FMA2(acc[1][0], h1, w0); FMA2(acc[1][1], h1, w1); FMA2(acc[1][2], h1, w2); FMA2(acc[1][3], h1, w3);
            FMA2(acc[2][0], h2, w0); FMA2(acc[2][1], h2, w1); FMA2(acc[2][2], h2, w2); FMA2(acc[2][3], h2, w3);
            FMA2(acc[3][0], h3, w0); FMA2(acc[3][1], h3, w1); FMA2(acc[3][2], h3, w2); FMA2(acc[3][3], h3, w3);
        }

        // ---- elementwise LSTM cell update (c stays in registers) ----
        float hnew[8];
        #pragma unroll
        for (int r2 = 0; r2 < 4; ++r2) {
            float gi0, gi1, gf0, gf1, gg0, gg1, go0, go1;
            upk2(acc[r2][0], gi0, gi1);
            upk2(acc[r2][1], gf0, gf1);
            upk2(acc[r2][2], gg0, gg1);
            upk2(acc[r2][3], go0, go1);
            {
                const int r = 2 * r2;
                float iv = sigf(gi0), fv = sigf(gf0), gv = tanh_(gg0), ov = sigf(go0);
                creg[r] = fv * creg[r] + iv * gv;
                hnew[r] = ov * tanh_(creg[r]);
            }
            {
                const int r = 2 * r2 + 1;
                float iv = sigf(gi1), fv = sigf(gf1), gv = tanh_(gg1), ov = sigf(go1);
                creg[r] = fv * creg[r] + iv * gv;
                hnew[r] = ov * tanh_(creg[r]);
            }
        }

        // write new h into the OTHER buffer; stage next x tile. No read-write hazard:
        // this step only read hT[t&1] / xT[t&1]; we write hT[(t+1)&1] / xT[(t+1)&1].
        {
            float* hd = hT + ((t + 1) & 1) * 64 * LDH + j * LDH + rbase;
            #pragma unroll
            for (int r = 0; r < 8; ++r) hd[r] = hnew[r];
        }
        if (pf) {
            float* xb2 = xT + ((t + 1) & 1) * 28 * LDH;
            #pragma unroll
            for (int u = 0; u < 4; ++u) {
                int e = u * NTHR + tid;
                if (e < RPB * I_) {
                    int r = e / 28, i2 = e - r * 28;
                    xb2[i2 * LDH + r] = xn[u];
                }
            }
        }
        __syncthreads();   // writes visible before next step reads them
    }

    // ---- final projection: out[b][o] = h_T[b] . Wout[o] + bout[o] ----
    const float* hf = hT + (T_ & 1) * 64 * LDH;
    for (int idx = tid; idx < RPB * O_; idx += NTHR) {
        int r = idx / O_, o = idx - r * O_;
        float s = bout[o];
        #pragma unroll
        for (int k = 0; k < 64; ++k)
            s += hf[k * LDH + r] * Wout[o * 64 + k];
        out[(row0 + r) * O_ + o] = s;
    }
}

extern "C" void kernel_launch(void* const* d_in, const int* in_sizes, int n_in,
                              void* d_out, int out_size)
{
    const float* x    = (const float*)d_in[0];
    const float* Wih  = (const float*)d_in[1];
    const float* Whh  = (const float*)d_in[2];
    const float* bih  = (const float*)d_in[3];
    const float* bhh  = (const float*)d_in[4];
    const float* Wout = (const float*)d_in[5];
    const float* bout = (const float*)d_in[6];
    float* out = (float*)d_out;

    const size_t smem = (size_t)SM_FLOATS * sizeof(float);  // ~107.5 KB per CTA
    cudaFuncSetAttribute(lstm_fused, cudaFuncAttributeMaxDynamicSharedMemorySize, (int)smem);
    lstm_fused<<<NBLK, NTHR, smem>>>(x, Wih, Whh, bih, bhh, Wout, bout, out);
}